// round 14
// baseline (speedup 1.0000x reference)
#include <cuda_runtime.h>

// GlobalContextAttention — j-pipelined fusion v3 (R10 + packing & MLP fixes).
// x (J, F, C=128) fp32, batch_index (F,) int32 SORTED, weight (C,C) fp32 -> out (J, B, C).
//
// R10 kept single-read traffic (510MB) and nearly matched the record with two
// defects: grid 256 underfilled the 296 resident slots (occ 41%), and the
// fused body held only 3 DRAM loads in flight/warp. v3: G_SPLIT=5 -> grid 640
// (resident capped at 296 by 2 CTAs/SM -> live L2 set ~89MB < 126MB), fused
// body streams 4 DRAM frames + 4 L2 frames per iter (L2 frames in 2 sub-batches
// of 2 to keep regs <= 64), reductions split across 256 threads.

static constexpr int C_DIM   = 128;
static constexpr int THREADS = 512;
static constexpr int WARPS   = 16;
static constexpr int G_SPLIT = 5;
static constexpr int MAX_SEG = 4096;

__device__ int g_seg[MAX_SEG + 1];

__global__ void seg_bounds_kernel(const int* __restrict__ idx, int Fn, int Bn)
{
    const int t = blockIdx.x * blockDim.x + threadIdx.x;
    if (t > Bn) return;
    int lo = 0, hi = Fn;
    while (lo < hi) {
        int m = (lo + hi) >> 1;
        if (idx[m] < t) lo = m + 1; else hi = m;
    }
    g_seg[t] = lo;
}

__device__ __forceinline__ float warp_gate(float d) {
#pragma unroll
    for (int s = 16; s > 0; s >>= 1)
        d += __shfl_xor_sync(0xffffffffu, d, s);
    return 1.f / (1.f + __expf(-d));
}

__global__ __launch_bounds__(THREADS, 2)
void gca_fused_kernel(const float* __restrict__ x,
                      const float* __restrict__ W,
                      float*       __restrict__ out,
                      int Jn, int Fn, int Bn)
{
    __shared__ float s_p1[WARPS * C_DIM];   // pass1 partials / gemv partials
    __shared__ float s_p2[WARPS * C_DIM];   // pass2 partials
    __shared__ float s_vec[C_DIM];          // mean, then gc

    const int tid  = threadIdx.x;
    const int warp = tid >> 5;
    const int lane = tid & 31;
    const int b    = blockIdx.x;
    const int g    = blockIdx.y;

    const int jb = (g * Jn) / G_SPLIT;
    const int je = ((g + 1) * Jn) / G_SPLIT;
    if (jb >= je) return;

    const int start = g_seg[b];
    const int end   = g_seg[b + 1];
    const int cnt   = end - start;
    const float inv_cnt = 1.0f / (float)(cnt > 0 ? cnt : 1);
    const int ch = lane * 4;

    // ================= prologue: pass1 for j = jb (unroll 6) =================
    {
        const float* xj = x + (size_t)jb * Fn * C_DIM;
        float4 acc = make_float4(0.f, 0.f, 0.f, 0.f);
        int f = start + warp;
        for (; f + 5 * WARPS < end; f += 6 * WARPS) {
#pragma unroll
            for (int u = 0; u < 6; u++) {
                const float4 a = *(const float4*)(xj + (size_t)(f + u * WARPS) * C_DIM + ch);
                acc.x += a.x; acc.y += a.y; acc.z += a.z; acc.w += a.w;
            }
        }
        for (; f < end; f += WARPS) {
            const float4 a = *(const float4*)(xj + (size_t)f * C_DIM + ch);
            acc.x += a.x; acc.y += a.y; acc.z += a.z; acc.w += a.w;
        }
        *(float4*)&s_p1[warp * C_DIM + ch] = acc;
    }
    __syncthreads();
    if (tid < C_DIM) {
        float s = 0.f;
#pragma unroll
        for (int w = 0; w < WARPS; w++) s += s_p1[w * C_DIM + tid];
        s_vec[tid] = s * inv_cnt;           // mean[jb,b,:]
    }
    __syncthreads();
    // gemv gc = tanh(mean @ W): 512 threads, k in 4 quarters of 32
    {
        const int t_out = tid & (C_DIM - 1);
        const int q     = tid >> 7;
        const float* wp = W + (size_t)(q * 32) * C_DIM + t_out;
        float p = 0.f;
#pragma unroll 8
        for (int k = 0; k < 32; k++)
            p += s_vec[q * 32 + k] * wp[(size_t)k * C_DIM];
        s_p1[q * C_DIM + t_out] = p;
    }
    __syncthreads();
    if (tid < C_DIM)
        s_vec[tid] = tanhf(s_p1[tid] + s_p1[C_DIM + tid] +
                           s_p1[2 * C_DIM + tid] + s_p1[3 * C_DIM + tid]);
    __syncthreads();

    // ================= steady state: pass1(j) fused with pass2(j-1) ==========
    for (int j = jb + 1; j < je; j++) {
        const float* xc = x + (size_t)j       * Fn * C_DIM;  // current (DRAM stream)
        const float* xp = x + (size_t)(j - 1) * Fn * C_DIM;  // previous (L2-hot)
        const float4 gc4 = *(const float4*)&s_vec[ch];

        float4 a1 = make_float4(0.f, 0.f, 0.f, 0.f);
        float4 a2 = make_float4(0.f, 0.f, 0.f, 0.f);
        int f = start + warp;
        for (; f + 3 * WARPS < end; f += 4 * WARPS) {
            // 4 DRAM loads issued first — deepest-latency stream gets max MLP
            const float4 n0 = *(const float4*)(xc + (size_t)(f            ) * C_DIM + ch);
            const float4 n1 = *(const float4*)(xc + (size_t)(f +     WARPS) * C_DIM + ch);
            const float4 n2 = *(const float4*)(xc + (size_t)(f + 2 * WARPS) * C_DIM + ch);
            const float4 n3 = *(const float4*)(xc + (size_t)(f + 3 * WARPS) * C_DIM + ch);
            // L2 frames in two sub-batches of 2 (caps live registers)
            {
                const float4 o0 = *(const float4*)(xp + (size_t)(f        ) * C_DIM + ch);
                const float4 o1 = *(const float4*)(xp + (size_t)(f + WARPS) * C_DIM + ch);
                float d0 = o0.x*gc4.x + o0.y*gc4.y + o0.z*gc4.z + o0.w*gc4.w;
                float d1 = o1.x*gc4.x + o1.y*gc4.y + o1.z*gc4.z + o1.w*gc4.w;
#pragma unroll
                for (int s = 16; s > 0; s >>= 1) {
                    d0 += __shfl_xor_sync(0xffffffffu, d0, s);
                    d1 += __shfl_xor_sync(0xffffffffu, d1, s);
                }
                const float g0 = 1.f / (1.f + __expf(-d0));
                const float g1 = 1.f / (1.f + __expf(-d1));
                a2.x += g0*o0.x + g1*o1.x; a2.y += g0*o0.y + g1*o1.y;
                a2.z += g0*o0.z + g1*o1.z; a2.w += g0*o0.w + g1*o1.w;
            }
            {
                const float4 o2 = *(const float4*)(xp + (size_t)(f + 2 * WARPS) * C_DIM + ch);
                const float4 o3 = *(const float4*)(xp + (size_t)(f + 3 * WARPS) * C_DIM + ch);
                float d2 = o2.x*gc4.x + o2.y*gc4.y + o2.z*gc4.z + o2.w*gc4.w;
                float d3 = o3.x*gc4.x + o3.y*gc4.y + o3.z*gc4.z + o3.w*gc4.w;
#pragma unroll
                for (int s = 16; s > 0; s >>= 1) {
                    d2 += __shfl_xor_sync(0xffffffffu, d2, s);
                    d3 += __shfl_xor_sync(0xffffffffu, d3, s);
                }
                const float g2 = 1.f / (1.f + __expf(-d2));
                const float g3 = 1.f / (1.f + __expf(-d3));
                a2.x += g2*o2.x + g3*o3.x; a2.y += g2*o2.y + g3*o3.y;
                a2.z += g2*o2.z + g3*o3.z; a2.w += g2*o2.w + g3*o3.w;
            }
            a1.x += n0.x + n1.x + n2.x + n3.x;
            a1.y += n0.y + n1.y + n2.y + n3.y;
            a1.z += n0.z + n1.z + n2.z + n3.z;
            a1.w += n0.w + n1.w + n2.w + n3.w;
        }
        for (; f < end; f += WARPS) {
            const float4 n0 = *(const float4*)(xc + (size_t)f * C_DIM + ch);
            const float4 o0 = *(const float4*)(xp + (size_t)f * C_DIM + ch);
            a1.x += n0.x; a1.y += n0.y; a1.z += n0.z; a1.w += n0.w;
            const float g0 = warp_gate(o0.x*gc4.x + o0.y*gc4.y + o0.z*gc4.z + o0.w*gc4.w);
            a2.x += g0*o0.x; a2.y += g0*o0.y; a2.z += g0*o0.z; a2.w += g0*o0.w;
        }
        *(float4*)&s_p1[warp * C_DIM + ch] = a1;
        *(float4*)&s_p2[warp * C_DIM + ch] = a2;
        __syncthreads();
        // parallel reductions: tid<128 -> out(j-1); tid in [128,256) -> mean(j)
        if (tid < C_DIM) {
            float s2 = 0.f;
#pragma unroll
            for (int w = 0; w < WARPS; w++) s2 += s_p2[w * C_DIM + tid];
            out[((size_t)(j - 1) * Bn + b) * C_DIM + tid] = s2 * inv_cnt;
        } else if (tid < 2 * C_DIM) {
            const int c = tid - C_DIM;
            float s1 = 0.f;
#pragma unroll
            for (int w = 0; w < WARPS; w++) s1 += s_p1[w * C_DIM + c];
            s_vec[c] = s1 * inv_cnt;        // mean[j,b,:]
        }
        __syncthreads();
        {
            const int t_out = tid & (C_DIM - 1);
            const int q     = tid >> 7;
            const float* wp = W + (size_t)(q * 32) * C_DIM + t_out;
            float p = 0.f;
#pragma unroll 8
            for (int k = 0; k < 32; k++)
                p += s_vec[q * 32 + k] * wp[(size_t)k * C_DIM];
            __syncthreads();                // mean reads done before s_p1 overwrite
            s_p1[q * C_DIM + t_out] = p;
        }
        __syncthreads();
        if (tid < C_DIM)
            s_vec[tid] = tanhf(s_p1[tid] + s_p1[C_DIM + tid] +
                               s_p1[2 * C_DIM + tid] + s_p1[3 * C_DIM + tid]);
        __syncthreads();
    }

    // ================= drain: pass2 for j = je-1 (unroll 4) =========
    {
        const float* xp = x + (size_t)(je - 1) * Fn * C_DIM;
        const float4 gc4 = *(const float4*)&s_vec[ch];
        float4 a2 = make_float4(0.f, 0.f, 0.f, 0.f);
        int f = start + warp;
        for (; f + 3 * WARPS < end; f += 4 * WARPS) {
            float4 o[4];
#pragma unroll
            for (int u = 0; u < 4; u++)
                o[u] = *(const float4*)(xp + (size_t)(f + u * WARPS) * C_DIM + ch);
            float d[4];
#pragma unroll
            for (int u = 0; u < 4; u++)
                d[u] = o[u].x*gc4.x + o[u].y*gc4.y + o[u].z*gc4.z + o[u].w*gc4.w;
#pragma unroll
            for (int s = 16; s > 0; s >>= 1) {
#pragma unroll
                for (int u = 0; u < 4; u++)
                    d[u] += __shfl_xor_sync(0xffffffffu, d[u], s);
            }
#pragma unroll
            for (int u = 0; u < 4; u++) {
                const float gg = 1.f / (1.f + __expf(-d[u]));
                a2.x += gg*o[u].x; a2.y += gg*o[u].y; a2.z += gg*o[u].z; a2.w += gg*o[u].w;
            }
        }
        for (; f < end; f += WARPS) {
            const float4 o0 = *(const float4*)(xp + (size_t)f * C_DIM + ch);
            const float gg = warp_gate(o0.x*gc4.x + o0.y*gc4.y + o0.z*gc4.z + o0.w*gc4.w);
            a2.x += gg*o0.x; a2.y += gg*o0.y; a2.z += gg*o0.z; a2.w += gg*o0.w;
        }
        *(float4*)&s_p2[warp * C_DIM + ch] = a2;
        __syncthreads();
        if (tid < C_DIM) {
            float s = 0.f;
#pragma unroll
            for (int w = 0; w < WARPS; w++) s += s_p2[w * C_DIM + tid];
            out[((size_t)(je - 1) * Bn + b) * C_DIM + tid] = s * inv_cnt;
        }
    }
}

extern "C" void kernel_launch(void* const* d_in, const int* in_sizes, int n_in,
                              void* d_out, int out_size)
{
    // Identify inputs by element count: x = largest; weight = C*C; idx = other multi-element.
    int xi = 0;
    for (int i = 1; i < n_in; i++)
        if (in_sizes[i] > in_sizes[xi]) xi = i;
    int wi = -1, ii = -1;
    for (int i = 0; i < n_in; i++) {
        if (i == xi) continue;
        if (in_sizes[i] == C_DIM * C_DIM && wi < 0) { wi = i; continue; }
        if (in_sizes[i] > 1 && ii < 0) ii = i;
    }
    if (wi < 0 || ii < 0) return;

    const float* x   = (const float*)d_in[xi];
    const int*   idx = (const int*)  d_in[ii];
    const float* W   = (const float*)d_in[wi];
    float*       out = (float*)d_out;

    const int Fn = in_sizes[ii];
    const int Jn = in_sizes[xi] / (Fn * C_DIM);
    int Bn = out_size / (Jn * C_DIM);
    if (Bn > MAX_SEG) Bn = MAX_SEG;

    const int gsplit = Jn < G_SPLIT ? Jn : G_SPLIT;
    seg_bounds_kernel<<<(Bn + 255) / 256 + 1, 256>>>(idx, Fn, Bn);
    dim3 grid(Bn, gsplit);
    gca_fused_kernel<<<grid, THREADS>>>(x, W, out, Jn, Fn, Bn);
}

// round 15
// speedup vs baseline: 1.0904x; 1.0904x over previous
#include <cuda_runtime.h>
#include <cstdint>

// GlobalContextAttention — R5 record kernel + bulk L2 prefetch of the slice.
// x (J, F, C=128) fp32, batch_index (F,) int32 SORTED, weight (C,C) fp32 -> out (J, B, C).
//
// R5 (139.6us) is DRAM-latency-starved: per-warp MLP caps pass1 at ~56% DRAM.
// R15: at CTA start, ~38 threads fire cp.async.bulk.prefetch.L2.global chunks
// covering the CTA's whole ~150KB slice. The prefetch engine gives DRAM an
// effectively unbounded request queue (no regs/smem/occupancy cost), and with
// CTA starts staggered across ~21 waves DRAM stays continuously fed. Pass1
// LDGs then hit L2 (~260cyc) where 32-warp x unroll-8 MLP saturates. L2 live
// set identical to R5 (~89MB: one slice per resident CTA, prefetch lines ==
// pass2 reuse lines). Occupancy pinned at 4 CTAs/SM via smem pad, as R5.

static constexpr int C_DIM   = 128;
static constexpr int THREADS = 256;
static constexpr int WARPS   = 8;
static constexpr int MAX_SEG = 4096;

__device__ int g_seg[MAX_SEG + 1];

__global__ void seg_bounds_kernel(const int* __restrict__ idx, int Fn, int Bn)
{
    const int t = blockIdx.x * blockDim.x + threadIdx.x;
    if (t > Bn) return;
    int lo = 0, hi = Fn;
    while (lo < hi) {
        int m = (lo + hi) >> 1;
        if (idx[m] < t) lo = m + 1; else hi = m;
    }
    g_seg[t] = lo;
}

__global__ __launch_bounds__(THREADS, 4)
void gca_fused_kernel(const float* __restrict__ x,
                      const float* __restrict__ W,
                      float*       __restrict__ out,
                      int Jn, int Fn, int Bn)
{
    __shared__ float s_red[WARPS][C_DIM];     // 4 KB working reduction buffer
    __shared__ float s_vec[C_DIM];            // mean, then gc (0.5 KB)
    __shared__ float s_pad[10624];            // 41.5 KB pad -> 4 CTAs/SM max

    const int tid  = threadIdx.x;
    const int warp = tid >> 5;
    const int lane = tid & 31;
    const int b    = blockIdx.x;
    const int j    = blockIdx.y;

    // Keep the pad alive without doing work (never true at runtime: Jn > 0).
    if (Jn < 0) s_pad[tid] = 0.f, out[tid] = s_pad[tid + 1];

    const int start = g_seg[b];
    const int end   = g_seg[b + 1];
    const int cnt   = end - start;
    const float inv_cnt = 1.0f / (float)(cnt > 0 ? cnt : 1);
    const int ch = lane * 4;                  // this lane's float4 channel group
    const float* xj = x + (size_t)j * Fn * C_DIM;

    // ---------------- L2 prefetch of the whole slice (fire-and-forget) -------
    {
        const char* sbase = (const char*)(xj + (size_t)start * C_DIM);
        const size_t slice_bytes = (size_t)cnt * C_DIM * 4;
        for (size_t off = (size_t)tid * 4096; off < slice_bytes;
             off += (size_t)THREADS * 4096) {
            const size_t rem = slice_bytes - off;
            const uint32_t sz = rem < 4096 ? (uint32_t)rem : 4096u;
            asm volatile("cp.async.bulk.prefetch.L2.global [%0], %1;"
                         :: "l"(sbase + off), "r"(sz) : "memory");
        }
    }

    // ---------------- pass 1: per-channel segment sum (unroll 8) -------------
    float4 acc = make_float4(0.f, 0.f, 0.f, 0.f);
    int f = start + warp;
    for (; f + 7 * WARPS < end; f += 8 * WARPS) {
#pragma unroll
        for (int u = 0; u < 8; u++) {
            const float4 a = *(const float4*)(xj + (size_t)(f + u * WARPS) * C_DIM + ch);
            acc.x += a.x; acc.y += a.y; acc.z += a.z; acc.w += a.w;
        }
    }
    for (; f < end; f += WARPS) {
        const float4 a = *(const float4*)(xj + (size_t)f * C_DIM + ch);
        acc.x += a.x; acc.y += a.y; acc.z += a.z; acc.w += a.w;
    }
    *(float4*)&s_red[warp][ch] = acc;
    __syncthreads();
    if (tid < C_DIM) {
        float s = 0.f;
#pragma unroll
        for (int w = 0; w < WARPS; w++) s += s_red[w][tid];
        s_vec[tid] = s * inv_cnt;             // mean[j,b,:]
    }
    __syncthreads();

    // ---------------- GEMV: gc = tanh(mean @ W) ----------------
    {
        const int t_out = tid & (C_DIM - 1);
        const int half  = tid >> 7;           // 0..1
        const float* wp = W + (size_t)(half * 64) * C_DIM + t_out;
        float p = 0.f;
#pragma unroll 8
        for (int k = 0; k < 64; k++)
            p += s_vec[half * 64 + k] * wp[(size_t)k * C_DIM];
        s_red[half][t_out] = p;
    }
    __syncthreads();
    if (tid < C_DIM)
        s_vec[tid] = tanhf(s_red[0][tid] + s_red[1][tid]);
    __syncthreads();

    // ---------------- pass 2: gate + gated segment mean (unroll 6) -----------
    const float4 gc4 = *(const float4*)&s_vec[ch];
    float4 oacc = make_float4(0.f, 0.f, 0.f, 0.f);
    f = start + warp;
    for (; f + 5 * WARPS < end; f += 6 * WARPS) {
        float4 a[6];
#pragma unroll
        for (int u = 0; u < 6; u++)
            a[u] = *(const float4*)(xj + (size_t)(f + u * WARPS) * C_DIM + ch);
        float d[6];
#pragma unroll
        for (int u = 0; u < 6; u++)
            d[u] = a[u].x*gc4.x + a[u].y*gc4.y + a[u].z*gc4.z + a[u].w*gc4.w;
#pragma unroll
        for (int s = 16; s > 0; s >>= 1) {
#pragma unroll
            for (int u = 0; u < 6; u++)
                d[u] += __shfl_xor_sync(0xffffffffu, d[u], s);
        }
#pragma unroll
        for (int u = 0; u < 6; u++) {
            const float g = 1.f / (1.f + __expf(-d[u]));
            oacc.x += g*a[u].x; oacc.y += g*a[u].y; oacc.z += g*a[u].z; oacc.w += g*a[u].w;
        }
    }
    for (; f < end; f += WARPS) {
        const float4 a = *(const float4*)(xj + (size_t)f * C_DIM + ch);
        float d = a.x*gc4.x + a.y*gc4.y + a.z*gc4.z + a.w*gc4.w;
#pragma unroll
        for (int s = 16; s > 0; s >>= 1)
            d += __shfl_xor_sync(0xffffffffu, d, s);
        const float g = 1.f / (1.f + __expf(-d));
        oacc.x += g*a.x; oacc.y += g*a.y; oacc.z += g*a.z; oacc.w += g*a.w;
    }
    *(float4*)&s_red[warp][ch] = oacc;
    __syncthreads();
    if (tid < C_DIM) {
        float s = 0.f;
#pragma unroll
        for (int w = 0; w < WARPS; w++) s += s_red[w][tid];
        out[((size_t)j * Bn + b) * C_DIM + tid] = s * inv_cnt;
    }
}

extern "C" void kernel_launch(void* const* d_in, const int* in_sizes, int n_in,
                              void* d_out, int out_size)
{
    // Identify inputs by element count: x = largest; weight = C*C; idx = other multi-element.
    int xi = 0;
    for (int i = 1; i < n_in; i++)
        if (in_sizes[i] > in_sizes[xi]) xi = i;
    int wi = -1, ii = -1;
    for (int i = 0; i < n_in; i++) {
        if (i == xi) continue;
        if (in_sizes[i] == C_DIM * C_DIM && wi < 0) { wi = i; continue; }
        if (in_sizes[i] > 1 && ii < 0) ii = i;
    }
    if (wi < 0 || ii < 0) return;

    const float* x   = (const float*)d_in[xi];
    const int*   idx = (const int*)  d_in[ii];
    const float* W   = (const float*)d_in[wi];
    float*       out = (float*)d_out;

    const int Fn = in_sizes[ii];
    const int Jn = in_sizes[xi] / (Fn * C_DIM);
    int Bn = out_size / (Jn * C_DIM);
    if (Bn > MAX_SEG) Bn = MAX_SEG;

    seg_bounds_kernel<<<(Bn + 255) / 256 + 1, 256>>>(idx, Fn, Bn);
    dim3 grid(Bn, Jn);
    gca_fused_kernel<<<grid, THREADS>>>(x, W, out, Jn, Fn, Bn);
}

// round 17
// speedup vs baseline: 1.1964x; 1.0972x over previous
#include <cuda_runtime.h>

// GlobalContextAttention — R5 record kernel + 16-lane-group pass2 reduction.
// x (J, F, C=128) fp32, batch_index (F,) int32 SORTED, weight (C,C) fp32 -> out (J, B, C).
//
// redux.sync.add.f32 is NOT available on sm_103 (R16 build fail). Same goal
// without it: pass2 uses 16-lane groups, each owning one frame with 8 channels
// per lane. Butterfly depth 4 (vs 5), 2 frames per warp sweep, all 32 lanes
// stay converged at every shfl (tail iterates on a CTA-uniform frame base with
// zero-padded loads). Everything else identical to R5: 256 thr, occupancy
// pinned at 4 CTAs/SM via smem pad (proven single-read L2 regime), pass1
// unroll 8, seg-bounds precomputed.

static constexpr int C_DIM   = 128;
static constexpr int THREADS = 256;
static constexpr int WARPS   = 8;
static constexpr int MAX_SEG = 4096;

__device__ int g_seg[MAX_SEG + 1];

__global__ void seg_bounds_kernel(const int* __restrict__ idx, int Fn, int Bn)
{
    const int t = blockIdx.x * blockDim.x + threadIdx.x;
    if (t > Bn) return;
    int lo = 0, hi = Fn;
    while (lo < hi) {
        int m = (lo + hi) >> 1;
        if (idx[m] < t) lo = m + 1; else hi = m;
    }
    g_seg[t] = lo;
}

__global__ __launch_bounds__(THREADS, 4)
void gca_fused_kernel(const float* __restrict__ x,
                      const float* __restrict__ W,
                      float*       __restrict__ out,
                      int Jn, int Fn, int Bn)
{
    __shared__ float s_red[2 * WARPS][C_DIM];  // 8 KB (pass1 uses 8 rows, pass2 uses 16)
    __shared__ float s_vec[C_DIM];             // mean, then gc
    __shared__ float s_pad[9600];              // 37.5 KB pad -> ~46 KB total -> 4 CTAs/SM

    const int tid  = threadIdx.x;
    const int warp = tid >> 5;
    const int lane = tid & 31;
    const int b    = blockIdx.x;
    const int j    = blockIdx.y;

    // Keep the pad alive without doing work (never true at runtime: Jn > 0).
    if (Jn < 0) s_pad[tid] = 0.f, out[tid] = s_pad[tid + 1];

    const int start = g_seg[b];
    const int end   = g_seg[b + 1];
    const int cnt   = end - start;
    const float inv_cnt = 1.0f / (float)(cnt > 0 ? cnt : 1);
    const int ch = lane * 4;                   // pass1 channel group
    const float* xj = x + (size_t)j * Fn * C_DIM;

    // ---------------- pass 1: per-channel segment sum (unroll 8) -------------
    float4 acc = make_float4(0.f, 0.f, 0.f, 0.f);
    int f = start + warp;
    for (; f + 7 * WARPS < end; f += 8 * WARPS) {
#pragma unroll
        for (int u = 0; u < 8; u++) {
            const float4 a = *(const float4*)(xj + (size_t)(f + u * WARPS) * C_DIM + ch);
            acc.x += a.x; acc.y += a.y; acc.z += a.z; acc.w += a.w;
        }
    }
    for (; f < end; f += WARPS) {
        const float4 a = *(const float4*)(xj + (size_t)f * C_DIM + ch);
        acc.x += a.x; acc.y += a.y; acc.z += a.z; acc.w += a.w;
    }
    *(float4*)&s_red[warp][ch] = acc;
    __syncthreads();
    if (tid < C_DIM) {
        float s = 0.f;
#pragma unroll
        for (int w = 0; w < WARPS; w++) s += s_red[w][tid];
        s_vec[tid] = s * inv_cnt;              // mean[j,b,:]
    }
    __syncthreads();

    // ---------------- GEMV: gc = tanh(mean @ W) ----------------
    {
        const int t_out = tid & (C_DIM - 1);
        const int half  = tid >> 7;            // 0..1
        const float* wp = W + (size_t)(half * 64) * C_DIM + t_out;
        float p = 0.f;
#pragma unroll 8
        for (int k = 0; k < 64; k++)
            p += s_vec[half * 64 + k] * wp[(size_t)k * C_DIM];
        s_red[half][t_out] = p;
    }
    __syncthreads();
    if (tid < C_DIM)
        s_vec[tid] = tanhf(s_red[0][tid] + s_red[1][tid]);
    __syncthreads();

    // ---------------- pass 2: 16-lane groups, 8 channels/lane -----------------
    // Group (warp, half) owns frame fb + 2*warp + half; sweep stride 16 frames.
    const int sl   = lane & 15;                // sub-lane within group
    const int half = lane >> 4;                // group id within warp
    const int ch8  = sl * 8;                   // this lane's 8 channels
    const float4 gA = *(const float4*)&s_vec[ch8];
    const float4 gB = *(const float4*)&s_vec[ch8 + 4];
    float4 oA = make_float4(0.f, 0.f, 0.f, 0.f);
    float4 oB = make_float4(0.f, 0.f, 0.f, 0.f);
    const int foff = 2 * warp + half;          // frame offset of this group

    int fb = start;
    for (; fb + 48 <= end; fb += 48) {         // 3 sweeps of 16 frames
        float4 aA[3], aB[3];
#pragma unroll
        for (int u = 0; u < 3; u++) {
            const float* fp = xj + (size_t)(fb + foff + 16 * u) * C_DIM + ch8;
            aA[u] = *(const float4*)(fp);
            aB[u] = *(const float4*)(fp + 4);
        }
        float d[3];
#pragma unroll
        for (int u = 0; u < 3; u++)
            d[u] = aA[u].x*gA.x + aA[u].y*gA.y + aA[u].z*gA.z + aA[u].w*gA.w
                 + aB[u].x*gB.x + aB[u].y*gB.y + aB[u].z*gB.z + aB[u].w*gB.w;
#pragma unroll
        for (int s = 8; s > 0; s >>= 1) {      // 4-step butterfly within 16 lanes
#pragma unroll
            for (int u = 0; u < 3; u++)
                d[u] += __shfl_xor_sync(0xffffffffu, d[u], s);
        }
#pragma unroll
        for (int u = 0; u < 3; u++) {
            const float g = 1.f / (1.f + __expf(-d[u]));
            oA.x += g*aA[u].x; oA.y += g*aA[u].y; oA.z += g*aA[u].z; oA.w += g*aA[u].w;
            oB.x += g*aB[u].x; oB.y += g*aB[u].y; oB.z += g*aB[u].z; oB.w += g*aB[u].w;
        }
    }
    for (; fb < end; fb += 16) {               // tail: uniform base, zero-padded
        const int fr = fb + foff;
        float4 aA2 = make_float4(0.f, 0.f, 0.f, 0.f);
        float4 aB2 = make_float4(0.f, 0.f, 0.f, 0.f);
        if (fr < end) {
            const float* fp = xj + (size_t)fr * C_DIM + ch8;
            aA2 = *(const float4*)(fp);
            aB2 = *(const float4*)(fp + 4);
        }
        float d = aA2.x*gA.x + aA2.y*gA.y + aA2.z*gA.z + aA2.w*gA.w
                + aB2.x*gB.x + aB2.y*gB.y + aB2.z*gB.z + aB2.w*gB.w;
#pragma unroll
        for (int s = 8; s > 0; s >>= 1)
            d += __shfl_xor_sync(0xffffffffu, d, s);
        const float g = 1.f / (1.f + __expf(-d));
        oA.x += g*aA2.x; oA.y += g*aA2.y; oA.z += g*aA2.z; oA.w += g*aA2.w;
        oB.x += g*aB2.x; oB.y += g*aB2.y; oB.z += g*aB2.z; oB.w += g*aB2.w;
    }

    __syncthreads();                           // s_red free
    *(float4*)&s_red[warp * 2 + half][ch8]     = oA;
    *(float4*)&s_red[warp * 2 + half][ch8 + 4] = oB;
    __syncthreads();
    if (tid < C_DIM) {
        float s = 0.f;
#pragma unroll
        for (int w = 0; w < 2 * WARPS; w++) s += s_red[w][tid];
        out[((size_t)j * Bn + b) * C_DIM + tid] = s * inv_cnt;
    }
}

extern "C" void kernel_launch(void* const* d_in, const int* in_sizes, int n_in,
                              void* d_out, int out_size)
{
    // Identify inputs by element count: x = largest; weight = C*C; idx = other multi-element.
    int xi = 0;
    for (int i = 1; i < n_in; i++)
        if (in_sizes[i] > in_sizes[xi]) xi = i;
    int wi = -1, ii = -1;
    for (int i = 0; i < n_in; i++) {
        if (i == xi) continue;
        if (in_sizes[i] == C_DIM * C_DIM && wi < 0) { wi = i; continue; }
        if (in_sizes[i] > 1 && ii < 0) ii = i;
    }
    if (wi < 0 || ii < 0) return;

    const float* x   = (const float*)d_in[xi];
    const int*   idx = (const int*)  d_in[ii];
    const float* W   = (const float*)d_in[wi];
    float*       out = (float*)d_out;

    const int Fn = in_sizes[ii];
    const int Jn = in_sizes[xi] / (Fn * C_DIM);
    int Bn = out_size / (Jn * C_DIM);
    if (Bn > MAX_SEG) Bn = MAX_SEG;

    seg_bounds_kernel<<<(Bn + 255) / 256 + 1, 256>>>(idx, Fn, Bn);
    dim3 grid(Bn, Jn);
    gca_fused_kernel<<<grid, THREADS>>>(x, W, out, Jn, Fn, Bn);
}